// round 9
// baseline (speedup 1.0000x reference)
#include <cuda_runtime.h>
#include <float.h>

// NormmaxBisect, alpha = 1.5, n_iter = 50, d = 2048.
// p = max(x - tau, 0)^2 ; p^alpha = max(x - tau, 0)^3.
// Only elements with x > max-1 can be nonzero. Output = zero-fill + scatter.
// tau* via Newton on f(tau) = sum c^3 - 1 (convex, decreasing; started on the
// f>=0 side => monotone quadratic convergence) with warp-uniform early exit:
// lands within ~1 ulp of the reference's 50-step fp32 bisection.
//
// Round-8 row algorithm, software-pipelined: each block walks RPB consecutive
// rows; after row i's gather barrier, ALL warps issue row i+1's loads and
// zero-fill before the (rotating) tail warp runs row i's Newton+scatter, so
// next-row LDG latency hides under the serial tail. SMEM double-buffered.

constexpr int   D       = 2048;
constexpr int   THREADS = 256;
constexpr int   NW      = THREADS / 32;
constexpr int   CAP     = 128;                        // >> E[#candidates] ~ 14
constexpr int   RPB     = 8;                          // rows per block
constexpr float TAU_HI_OFF = 0.022097086912079612f;   // (1/2048)^0.5

__global__ void __launch_bounds__(THREADS)
normmax_kernel(const float* __restrict__ X, float* __restrict__ Out, int nrows)
{
    __shared__ float s_cand[2][CAP];
    __shared__ int   s_pos[2][CAP];
    __shared__ float s_red[2][NW];
    __shared__ int   s_cnt[2];

    const int t    = threadIdx.x;
    const int lane = t & 31;
    const int wid  = t >> 5;

    const int row0 = (int)blockIdx.x * RPB;
    if (row0 >= nrows) return;                       // uniform per block
    const int rows_here = min(RPB, nrows - row0);

    const float4 z4 = make_float4(0.f, 0.f, 0.f, 0.f);

    // ---- Prologue: load + zero-fill row 0 ----
    size_t base = (size_t)row0 * D;
    {
        const float4* xin  = reinterpret_cast<const float4*>(X + base);
        float4*       xout = reinterpret_cast<float4*>(Out + base);
        // issued here; consumed after the reduction below
        float4 p0 = xin[t];
        float4 p1 = xin[t + THREADS];
        xout[t]           = z4;
        xout[t + THREADS] = z4;
        // stash via registers (fall through into loop-carried v0/v1)
        s_red[0][0] = 0.f;  // (dead store placeholder removed by compiler)
        // carry:
        asm volatile("" ::: "memory");
        // v0/v1 declared below; assign now
        // (declaration hoisted)
        // -- handled by initializing v0/v1 here:
        (void)p0; (void)p1;
        // NOTE: real carry done just below to keep v0/v1 in scope.
    }
    // loop-carried row data
    float4 v0, v1;
    {
        const float4* xin = reinterpret_cast<const float4*>(X + base);
        v0 = xin[t];
        v1 = xin[t + THREADS];
    }

#pragma unroll 1
    for (int i = 0; i < RPB; ++i) {
        if (i >= rows_here) break;
        const int buf = i & 1;
        const size_t rbase = base;

        // reset this buffer's counter (its previous reader finished before the
        // previous barrier A; atomics on it only happen after barrier A below)
        if (t == 0) s_cnt[buf] = 0;

        float x0 = v0.x, x1 = v0.y, x2 = v0.z, x3 = v0.w;
        float x4 = v1.x, x5 = v1.y, x6 = v1.z, x7 = v1.w;

        float m = fmaxf(fmaxf(fmaxf(x0, x1), fmaxf(x2, x3)),
                        fmaxf(fmaxf(x4, x5), fmaxf(x6, x7)));
#pragma unroll
        for (int o = 16; o; o >>= 1)
            m = fmaxf(m, __shfl_xor_sync(0xffffffffu, m, o));
        if (lane == 0) s_red[buf][wid] = m;
        __syncthreads();                                   // barrier A(i)

        float maxval = s_red[buf][0];
#pragma unroll
        for (int w = 1; w < NW; ++w) maxval = fmaxf(maxval, s_red[buf][w]);
        const float thresh = maxval - 1.0f;

        // ---- Gather candidates into buf ----
        unsigned mm = 0;
        mm |= (x0 > thresh) ? 1u   : 0u;
        mm |= (x1 > thresh) ? 2u   : 0u;
        mm |= (x2 > thresh) ? 4u   : 0u;
        mm |= (x3 > thresh) ? 8u   : 0u;
        mm |= (x4 > thresh) ? 16u  : 0u;
        mm |= (x5 > thresh) ? 32u  : 0u;
        mm |= (x6 > thresh) ? 64u  : 0u;
        mm |= (x7 > thresh) ? 128u : 0u;
        if (mm) {
            int p = atomicAdd(&s_cnt[buf], __popc(mm));
            float xv[8] = {x0, x1, x2, x3, x4, x5, x6, x7};
#pragma unroll
            for (int q = 0; q < 8; ++q) {
                if ((mm >> q) & 1) {
                    if (p < CAP) {
                        s_cand[buf][p] = xv[q];
                        s_pos[buf][p]  = 4 * t + (q >> 2) * (4 * THREADS) + (q & 3);
                    }
                    ++p;
                }
            }
        }
        __syncthreads();                                   // barrier B(i)
        const int n = s_cnt[buf];

        // ---- Pipeline: issue NEXT row's loads + zero-fill BEFORE tail work ----
        const size_t nbase = rbase + D;
        if (i + 1 < rows_here) {
            const float4* nxin  = reinterpret_cast<const float4*>(X + nbase);
            float4*       nxout = reinterpret_cast<float4*>(Out + nbase);
            v0 = nxin[t];
            v1 = nxin[t + THREADS];
            nxout[t]           = z4;
            nxout[t + THREADS] = z4;
        }

        // ---- Tail: one warp (rotating) finishes this row ----
        if (wid == (int)((blockIdx.x + (unsigned)i) & (unsigned)(NW - 1))) {
            const float tau_hi = maxval - TAU_HI_OFF;      // f(tau_hi) < 0

            if (n <= CAP) {
                const float SENT = -1.0e30f;               // exact 0 via fmaxf
                float cv0 = (lane      < n) ? s_cand[buf][lane]      : SENT;
                float cv1 = (lane + 32 < n) ? s_cand[buf][lane + 32] : SENT;
                float cv2 = (lane + 64 < n) ? s_cand[buf][lane + 64] : SENT;
                float cv3 = (lane + 96 < n) ? s_cand[buf][lane + 96] : SENT;

                float tau = thresh;                        // f(thresh) >= 0
#pragma unroll 1
                for (int it = 0; it < 8; ++it) {
                    float c0 = fmaxf(cv0 - tau, 0.f), q0 = c0 * c0;
                    float c1 = fmaxf(cv1 - tau, 0.f), q1 = c1 * c1;
                    float c2 = fmaxf(cv2 - tau, 0.f), q2 = c2 * c2;
                    float c3 = fmaxf(cv3 - tau, 0.f), q3 = c3 * c3;
                    float a = (q0 + q1) + (q2 + q3);                              // sum c^2
                    float b = fmaf(q0, c0, fmaf(q1, c1, fmaf(q2, c2, q3 * c3))); // sum c^3
#pragma unroll
                    for (int o = 16; o; o >>= 1) {         // 2 chains pipeline
                        a += __shfl_xor_sync(0xffffffffu, a, o);
                        b += __shfl_xor_sync(0xffffffffu, b, o);
                    }
                    // f = b-1, f' = -3a (a >= (maxval-tau)^2 > 0 while tau<=tau_hi)
                    float nt = tau + (b - 1.0f) / (3.0f * a);
                    nt = fminf(fmaxf(nt, thresh), tau_hi);
                    if (nt == tau) break;                  // warp-uniform
                    tau = nt;
                }

                float c0 = fmaxf(cv0 - tau, 0.f), q0 = c0 * c0;
                float c1 = fmaxf(cv1 - tau, 0.f), q1 = c1 * c1;
                float c2 = fmaxf(cv2 - tau, 0.f), q2 = c2 * c2;
                float c3 = fmaxf(cv3 - tau, 0.f), q3 = c3 * c3;
                float S = (q0 + q1) + (q2 + q3);
#pragma unroll
                for (int o = 16; o; o >>= 1) S += __shfl_xor_sync(0xffffffffu, S, o);
                const float invS = 1.0f / S;

                if (lane      < n) Out[rbase + s_pos[buf][lane]]      = q0 * invS;
                if (lane + 32 < n) Out[rbase + s_pos[buf][lane + 32]] = q1 * invS;
                if (lane + 64 < n) Out[rbase + s_pos[buf][lane + 64]] = q2 * invS;
                if (lane + 96 < n) Out[rbase + s_pos[buf][lane + 96]] = q3 * invS;
            } else {
                // Dense fallback (statistically never): reference bisection,
                // this warp only, row re-read through L2.
                float tau_lo = thresh;
                float dm     = tau_hi - tau_lo;
                float tau_m  = tau_lo;
                for (int it = 0; it < 50; ++it) {
                    dm *= 0.5f;
                    tau_m = tau_lo + dm;
                    if (tau_m == tau_lo) break;
                    float s = 0.f;
                    for (int j = lane; j < D; j += 32) {
                        float c = fmaxf(X[rbase + j] - tau_m, 0.f);
                        s = fmaf(c * c, c, s);
                    }
#pragma unroll
                    for (int o = 16; o; o >>= 1) s += __shfl_xor_sync(0xffffffffu, s, o);
                    if (s >= 1.0f) tau_lo = tau_m;
                }
                float S = 0.f;
                for (int j = lane; j < D; j += 32) {
                    float c = fmaxf(X[rbase + j] - tau_m, 0.f);
                    S = fmaf(c, c, S);
                }
#pragma unroll
                for (int o = 16; o; o >>= 1) S += __shfl_xor_sync(0xffffffffu, S, o);
                const float invS = 1.0f / S;
                for (int j = lane; j < D; j += 32) {
                    float c = fmaxf(X[rbase + j] - tau_m, 0.f);
                    Out[rbase + j] = c * c * invS;
                }
            }
        }
        base = nbase;
    }
}

extern "C" void kernel_launch(void* const* d_in, const int* in_sizes, int n_in,
                              void* d_out, int out_size) {
    const float* X = (const float*)d_in[0];
    float* Out = (float*)d_out;
    int nrows = out_size / D;
    int nblocks = (nrows + RPB - 1) / RPB;
    normmax_kernel<<<nblocks, THREADS>>>(X, Out, nrows);
}

// round 10
// speedup vs baseline: 1.0201x; 1.0201x over previous
#include <cuda_runtime.h>
#include <float.h>

// NormmaxBisect, alpha = 1.5, n_iter = 50, d = 2048.
// p = max(x - tau, 0)^2 ; p^alpha = max(x - tau, 0)^3.
// Only elements with x > max-1 can be nonzero. Output = zero-fill + scatter.
// tau* via Newton on f(tau) = sum c^3 - 1 (convex, decreasing; start on the
// f>=0 side => monotone quadratic convergence, warp-uniform early exit);
// lands within ~1 ulp of the reference's 50-step fp32 bisection.
//
// TWO-KERNEL SPLIT: kernel A is pure streaming (load, block-max, gather
// candidates to global scratch, zero-fill output) with NO serial tail gating
// block turnover; kernel B (one warp per row) solves Newton and scatters the
// ~14 nonzero outputs per row.

constexpr int   D       = 2048;
constexpr int   THREADS = 256;
constexpr int   CAP     = 128;                        // >> E[#candidates] ~ 14
constexpr int   NROWS_MAX = 65536;                    // 2*16*2048
constexpr int   WPB     = THREADS / 32;               // rows per block, kernel B
constexpr float TAU_HI_OFF = 0.022097086912079612f;   // (1/2048)^0.5

// Scratch (static device globals -- allowed; no runtime allocation).
__device__ float  g_vals[(size_t)NROWS_MAX * CAP];
__device__ int    g_pos [(size_t)NROWS_MAX * CAP];
__device__ float2 g_hdr [NROWS_MAX];                  // {maxval, n as int bits}

// ---------------- Kernel A: stream + gather, no tail ----------------
__global__ void __launch_bounds__(THREADS)
gather_kernel(const float* __restrict__ X, float* __restrict__ Out)
{
    __shared__ float s_red[THREADS / 32];
    __shared__ int   s_cnt;

    const int row  = blockIdx.x;
    const size_t base = (size_t)row * D;
    const float4* __restrict__ xin  = reinterpret_cast<const float4*>(X + base);
    float4* __restrict__       xout = reinterpret_cast<float4*>(Out + base);

    const int t    = threadIdx.x;
    const int lane = t & 31;
    const int wid  = t >> 5;
    if (t == 0) s_cnt = 0;

    // ---- Load 8 elems/thread, zero-fill output, block max ----
    float4 v0 = xin[t];
    float4 v1 = xin[t + THREADS];
    const float4 z4 = make_float4(0.f, 0.f, 0.f, 0.f);
    xout[t]           = z4;
    xout[t + THREADS] = z4;

    float x0 = v0.x, x1 = v0.y, x2 = v0.z, x3 = v0.w;
    float x4 = v1.x, x5 = v1.y, x6 = v1.z, x7 = v1.w;

    float m = fmaxf(fmaxf(fmaxf(x0, x1), fmaxf(x2, x3)),
                    fmaxf(fmaxf(x4, x5), fmaxf(x6, x7)));
#pragma unroll
    for (int o = 16; o; o >>= 1)
        m = fmaxf(m, __shfl_xor_sync(0xffffffffu, m, o));
    if (lane == 0) s_red[wid] = m;
    __syncthreads();

    float maxval = s_red[0];
#pragma unroll
    for (int w = 1; w < THREADS / 32; ++w) maxval = fmaxf(maxval, s_red[w]);
    const float thresh = maxval - 1.0f;

    // ---- Gather candidates straight to global scratch ----
    unsigned mm = 0;
    mm |= (x0 > thresh) ? 1u   : 0u;
    mm |= (x1 > thresh) ? 2u   : 0u;
    mm |= (x2 > thresh) ? 4u   : 0u;
    mm |= (x3 > thresh) ? 8u   : 0u;
    mm |= (x4 > thresh) ? 16u  : 0u;
    mm |= (x5 > thresh) ? 32u  : 0u;
    mm |= (x6 > thresh) ? 64u  : 0u;
    mm |= (x7 > thresh) ? 128u : 0u;
    if (mm) {   // ~5% of threads
        int p = atomicAdd(&s_cnt, __popc(mm));
        const size_t sbase = (size_t)row * CAP;
        float xv[8] = {x0, x1, x2, x3, x4, x5, x6, x7};
#pragma unroll
        for (int i = 0; i < 8; ++i) {
            if ((mm >> i) & 1) {
                if (p < CAP) {
                    g_vals[sbase + p] = xv[i];
                    g_pos [sbase + p] = 4 * t + (i >> 2) * (4 * THREADS) + (i & 3);
                }
                ++p;
            }
        }
    }
    __syncthreads();
    if (t == 0) g_hdr[row] = make_float2(maxval, __int_as_float(s_cnt));
}

// ---------------- Kernel B: one warp per row, Newton + scatter ----------------
__global__ void __launch_bounds__(THREADS)
solve_kernel(const float* __restrict__ X, float* __restrict__ Out, int nrows)
{
    const int lane = threadIdx.x & 31;
    const int row  = blockIdx.x * WPB + (threadIdx.x >> 5);
    if (row >= nrows) return;

    const size_t base  = (size_t)row * D;
    const size_t sbase = (size_t)row * CAP;

    const float2 hdr = g_hdr[row];          // broadcast 8B load per warp
    const float maxval = hdr.x;
    const int   n      = __float_as_int(hdr.y);
    const float thresh = maxval - 1.0f;
    const float tau_hi = maxval - TAU_HI_OFF;   // f(tau_hi) < 0 always

    if (n <= CAP) {
        // ---- Newton, lane-parallel over <=128 candidates in registers ----
        const float SENT = -1.0e30f;        // contributes exactly 0 via fmaxf
        float cv0 = (lane      < n) ? g_vals[sbase + lane]      : SENT;
        float cv1 = (lane + 32 < n) ? g_vals[sbase + lane + 32] : SENT;
        float cv2 = (lane + 64 < n) ? g_vals[sbase + lane + 64] : SENT;
        float cv3 = (lane + 96 < n) ? g_vals[sbase + lane + 96] : SENT;

        float tau = thresh;                  // f(thresh) >= 0
#pragma unroll 1
        for (int it = 0; it < 8; ++it) {
            float c0 = fmaxf(cv0 - tau, 0.f), q0 = c0 * c0;
            float c1 = fmaxf(cv1 - tau, 0.f), q1 = c1 * c1;
            float c2 = fmaxf(cv2 - tau, 0.f), q2 = c2 * c2;
            float c3 = fmaxf(cv3 - tau, 0.f), q3 = c3 * c3;
            float a = (q0 + q1) + (q2 + q3);                              // sum c^2
            float b = fmaf(q0, c0, fmaf(q1, c1, fmaf(q2, c2, q3 * c3))); // sum c^3
#pragma unroll
            for (int o = 16; o; o >>= 1) {   // two independent chains pipeline
                a += __shfl_xor_sync(0xffffffffu, a, o);
                b += __shfl_xor_sync(0xffffffffu, b, o);
            }
            // f = b - 1, f' = -3a  (a >= (maxval-tau)^2 > 0 while tau <= tau_hi)
            float nt = tau + (b - 1.0f) / (3.0f * a);
            nt = fminf(fmaxf(nt, thresh), tau_hi);
            if (nt == tau) break;            // converged (warp-uniform: a,b
            tau = nt;                        // bit-identical on all lanes)
        }

        // ---- Final S = sum c^2 and scatter ----
        float c0 = fmaxf(cv0 - tau, 0.f), q0 = c0 * c0;
        float c1 = fmaxf(cv1 - tau, 0.f), q1 = c1 * c1;
        float c2 = fmaxf(cv2 - tau, 0.f), q2 = c2 * c2;
        float c3 = fmaxf(cv3 - tau, 0.f), q3 = c3 * c3;
        float S = (q0 + q1) + (q2 + q3);
#pragma unroll
        for (int o = 16; o; o >>= 1) S += __shfl_xor_sync(0xffffffffu, S, o);
        const float invS = 1.0f / S;

        if (lane      < n) Out[base + g_pos[sbase + lane]]      = q0 * invS;
        if (lane + 32 < n) Out[base + g_pos[sbase + lane + 32]] = q1 * invS;
        if (lane + 64 < n) Out[base + g_pos[sbase + lane + 64]] = q2 * invS;
        if (lane + 96 < n) Out[base + g_pos[sbase + lane + 96]] = q3 * invS;
    } else {
        // ---- Dense fallback (statistically never): exact reference bisection,
        //      this warp only, row re-read through L2. ----
        float tau_lo = thresh;
        float dm     = tau_hi - tau_lo;
        float tau_m  = tau_lo;
        for (int it = 0; it < 50; ++it) {
            dm *= 0.5f;
            tau_m = tau_lo + dm;
            if (tau_m == tau_lo) break;
            float s = 0.f;
            for (int j = lane; j < D; j += 32) {
                float c = fmaxf(X[base + j] - tau_m, 0.f);
                s = fmaf(c * c, c, s);
            }
#pragma unroll
            for (int o = 16; o; o >>= 1) s += __shfl_xor_sync(0xffffffffu, s, o);
            if (s >= 1.0f) tau_lo = tau_m;
        }
        float S = 0.f;
        for (int j = lane; j < D; j += 32) {
            float c = fmaxf(X[base + j] - tau_m, 0.f);
            S = fmaf(c, c, S);
        }
#pragma unroll
        for (int o = 16; o; o >>= 1) S += __shfl_xor_sync(0xffffffffu, S, o);
        const float invS = 1.0f / S;
        for (int j = lane; j < D; j += 32) {
            float c = fmaxf(X[base + j] - tau_m, 0.f);
            Out[base + j] = c * c * invS;
        }
    }
}

extern "C" void kernel_launch(void* const* d_in, const int* in_sizes, int n_in,
                              void* d_out, int out_size) {
    const float* X = (const float*)d_in[0];
    float* Out = (float*)d_out;
    int nrows = out_size / D;                    // 65536 for this problem
    gather_kernel<<<nrows, THREADS>>>(X, Out);
    solve_kernel<<<(nrows + WPB - 1) / WPB, THREADS>>>(X, Out, nrows);
}